// round 8
// baseline (speedup 1.0000x reference)
#include <cuda_runtime.h>

#define BB   512
#define CC   512
#define KK   512
#define EE   16
#define NT   256

#define Z_OFF   0
#define ZE_OFF  ((size_t)BB * CC * EE)            // 4,194,304 floats
#define OH_OFF  ((size_t)2 * BB * CC * EE)        // 8,388,608 floats

typedef unsigned long long u64;

__device__ unsigned g_ctr;                         // work-stealing cursor
__device__ int      g_idx[CC * BB];                // argmin scratch, [c][b]

__device__ __forceinline__ u64 pack2(float a, float b) {
    u64 r;
    asm("mov.b64 %0, {%1, %2};" : "=l"(r) : "f"(a), "f"(b));
    return r;
}
__device__ __forceinline__ void fma2(u64 &d, u64 a, u64 b) {
    asm("fma.rn.f32x2 %0, %1, %2, %0;" : "+l"(d) : "l"(a), "l"(b));
}
__device__ __forceinline__ void unpack2(float &lo, float &hi, u64 v) {
    asm("mov.b64 {%0, %1}, %2;" : "=f"(lo), "=f"(hi) : "l"(v));
}

// ---- concurrent zero-fill of one_hot: 64 KB chunks via work-stealing ----
#define CHUNK_F4   (NT * 16)                               // 4096 float4 = 64 KB
#define NCHUNK     (BB * CC * KK / 4 / CHUNK_F4)           // 8192
__global__ void __launch_bounds__(NT) zero_oh(float* __restrict__ out)
{
    __shared__ unsigned ch;
    float4* base = (float4*)(out + OH_OFF);
    const float4 z4 = make_float4(0.f, 0.f, 0.f, 0.f);
    for (;;) {
        if (threadIdx.x == 0) ch = atomicAdd(&g_ctr, 1u);
        __syncthreads();
        const unsigned c = ch;
        if (c >= NCHUNK) return;                           // uniform exit
        float4* p = base + (size_t)c * CHUNK_F4 + threadIdx.x;
#pragma unroll
        for (int i = 0; i < 16; i++) __stcs(p + i * NT, z4);
        __syncthreads();
    }
}

// ---- compute kernel: R2 loop, stores removed. 512 blocks, 2 rows/thread ----
// Dynamic smem (34,816 B): sdict float[KK*EE] (32 KB), snrm float[KK] (2 KB)
__global__ void __launch_bounds__(NT, 3) vq_kernel(const float* __restrict__ mu,
                                                   const float* __restrict__ dict,
                                                   float* __restrict__ out)
{
    extern __shared__ float smem_f[];
    float* sdict = smem_f;
    float* snrm  = smem_f + KK * EE;

    const int c = blockIdx.x;
    const int t = threadIdx.x;

    u64 muA[EE / 2], muB[EE / 2];
    {
        const float* m0 = mu + (size_t)t         * (CC * EE) + c * EE;
        const float* m1 = mu + (size_t)(t + 256) * (CC * EE) + c * EE;
#pragma unroll
        for (int e = 0; e < EE; e += 4) {
            float4 a = *(const float4*)(m0 + e);
            float4 b = *(const float4*)(m1 + e);
            muA[e / 2] = pack2(a.x, a.y);  muA[e / 2 + 1] = pack2(a.z, a.w);
            muB[e / 2] = pack2(b.x, b.y);  muB[e / 2 + 1] = pack2(b.z, b.w);
        }
    }
    {
        const float4* g = (const float4*)(dict + (size_t)c * KK * EE);
        float4* sd4 = (float4*)sdict;
#pragma unroll 4
        for (int i = t; i < KK * EE / 4; i += NT) sd4[i] = g[i];
    }
    __syncthreads();

#pragma unroll
    for (int k = t; k < KK; k += NT) {
        const float4* dv = (const float4*)(sdict + k * EE);
        float s = 0.f;
#pragma unroll
        for (int j = 0; j < 4; j++) {
            float4 v = dv[j];
            s = fmaf(v.x, v.x, s); s = fmaf(v.y, v.y, s);
            s = fmaf(v.z, v.z, s); s = fmaf(v.w, v.w, s);
        }
        snrm[k] = -0.5f * s;
    }
    __syncthreads();

    float best0 = -3.4e38f, best1 = -3.4e38f;
    int i0 = 0, i1 = 0;
    const ulonglong2* dq = (const ulonglong2*)sdict;

    for (int it = 0; it < KK / 2; ++it) {
        const int k = 2 * it;
        const float2 nn = *(const float2*)(snrm + k);
        float lo, hi, s;
        {   // k
            ulonglong2 q0 = dq[0], q1 = dq[1], q2 = dq[2], q3 = dq[3];
            u64 a0 = pack2(nn.x, 0.f), a1 = a0;
            fma2(a0, muA[0], q0.x); fma2(a1, muB[0], q0.x);
            fma2(a0, muA[1], q0.y); fma2(a1, muB[1], q0.y);
            fma2(a0, muA[2], q1.x); fma2(a1, muB[2], q1.x);
            fma2(a0, muA[3], q1.y); fma2(a1, muB[3], q1.y);
            fma2(a0, muA[4], q2.x); fma2(a1, muB[4], q2.x);
            fma2(a0, muA[5], q2.y); fma2(a1, muB[5], q2.y);
            fma2(a0, muA[6], q3.x); fma2(a1, muB[6], q3.x);
            fma2(a0, muA[7], q3.y); fma2(a1, muB[7], q3.y);
            unpack2(lo, hi, a0); s = lo + hi;
            if (s > best0) { best0 = s; i0 = k; }
            unpack2(lo, hi, a1); s = lo + hi;
            if (s > best1) { best1 = s; i1 = k; }
        }
        {   // k+1
            ulonglong2 q4 = dq[4], q5 = dq[5], q6 = dq[6], q7 = dq[7];
            u64 a2 = pack2(nn.y, 0.f), a3 = a2;
            fma2(a2, muA[0], q4.x); fma2(a3, muB[0], q4.x);
            fma2(a2, muA[1], q4.y); fma2(a3, muB[1], q4.y);
            fma2(a2, muA[2], q5.x); fma2(a3, muB[2], q5.x);
            fma2(a2, muA[3], q5.y); fma2(a3, muB[3], q5.y);
            fma2(a2, muA[4], q6.x); fma2(a3, muB[4], q6.x);
            fma2(a2, muA[5], q6.y); fma2(a3, muB[5], q6.y);
            fma2(a2, muA[6], q7.x); fma2(a3, muB[6], q7.x);
            fma2(a2, muA[7], q7.y); fma2(a3, muB[7], q7.y);
            unpack2(lo, hi, a2); s = lo + hi;
            if (s > best0) { best0 = s; i0 = k + 1; }
            unpack2(lo, hi, a3); s = lo + hi;
            if (s > best1) { best1 = s; i1 = k + 1; }
        }
        dq += 8;
    }

    // ---- z / z_embed; indices to scratch (ones land after the join) ----
    {
        const float* v = sdict + i0 * EE;
        size_t off = (size_t)t * (CC * EE) + c * EE;
#pragma unroll
        for (int e = 0; e < EE; e += 4) {
            float4 vv = *(const float4*)(v + e);
            float mx, my, mz, mw;
            unpack2(mx, my, muA[e / 2]);
            unpack2(mz, mw, muA[e / 2 + 1]);
            float4 zz;
            zz.x = mx + (vv.x - mx); zz.y = my + (vv.y - my);
            zz.z = mz + (vv.z - mz); zz.w = mw + (vv.w - mw);
            *(float4*)(out + Z_OFF  + off + e) = zz;
            *(float4*)(out + ZE_OFF + off + e) = vv;
        }
    }
    {
        const float* v = sdict + i1 * EE;
        size_t off = (size_t)(t + 256) * (CC * EE) + c * EE;
#pragma unroll
        for (int e = 0; e < EE; e += 4) {
            float4 vv = *(const float4*)(v + e);
            float mx, my, mz, mw;
            unpack2(mx, my, muB[e / 2]);
            unpack2(mz, mw, muB[e / 2 + 1]);
            float4 zz;
            zz.x = mx + (vv.x - mx); zz.y = my + (vv.y - my);
            zz.z = mz + (vv.z - mz); zz.w = mw + (vv.w - mw);
            *(float4*)(out + Z_OFF  + off + e) = zz;
            *(float4*)(out + ZE_OFF + off + e) = vv;
        }
    }
    g_idx[c * BB + t]       = i0;
    g_idx[c * BB + t + 256] = i1;
}

// ---- ones scatter (after zeros + indices) ----
__global__ void __launch_bounds__(NT) ones_kernel(float* __restrict__ out)
{
    const int tid = blockIdx.x * NT + threadIdx.x;   // 0 .. CC*BB-1
    const int c = tid >> 9;
    const int b = tid & (BB - 1);
    const int k = g_idx[tid];
    out[OH_OFF + (size_t)b * (CC * KK) + (size_t)c * KK + k] = 1.0f;
}

extern "C" void kernel_launch(void* const* d_in, const int* in_sizes, int n_in,
                              void* d_out, int out_size)
{
    (void)in_sizes; (void)n_in; (void)out_size;
    const float* mu   = (const float*)d_in[0];
    const float* dict = (const float*)d_in[1];
    float* out = (float*)d_out;

    // Fresh fork/join plumbing each call (never destroyed: a destroyed stream
    // would invalidate the capture; the function itself only runs a few times).
    cudaStream_t s2;
    cudaEvent_t evA, evB;
    int lo_pri, hi_pri;
    cudaDeviceGetStreamPriorityRange(&lo_pri, &hi_pri);
    cudaStreamCreateWithPriority(&s2, cudaStreamNonBlocking, hi_pri);
    cudaEventCreateWithFlags(&evA, cudaEventDisableTiming);
    cudaEventCreateWithFlags(&evB, cudaEventDisableTiming);

    unsigned* ctr_addr = nullptr;
    cudaGetSymbolAddress((void**)&ctr_addr, g_ctr);
    cudaMemsetAsync(ctr_addr, 0, sizeof(unsigned), 0);   // reset work cursor

    cudaEventRecord(evA, 0);
    cudaStreamWaitEvent(s2, evA, 0);
    zero_oh<<<592, NT, 0, s2>>>(out);                    // concurrent branch
    cudaEventRecord(evB, s2);

    const int smem = (KK * EE + KK) * 4;                 // 34,816 bytes
    cudaFuncSetAttribute(vq_kernel, cudaFuncAttributeMaxDynamicSharedMemorySize, smem);
    vq_kernel<<<CC, NT, smem, 0>>>(mu, dict, out);       // parallel with zero_oh

    cudaStreamWaitEvent(0, evB, 0);                      // join
    ones_kernel<<<CC * BB / NT, NT, 0, 0>>>(out);
}

// round 10
// speedup vs baseline: 1.3877x; 1.3877x over previous
#include <cuda_runtime.h>

#define BB   512
#define CC   512
#define KK   512
#define EE   16
#define NT   256

#define Z_OFF   0
#define ZE_OFF  ((size_t)BB * CC * EE)            // 4,194,304 floats
#define OH_OFF  ((size_t)2 * BB * CC * EE)        // 8,388,608 floats

typedef unsigned long long u64;

__device__ __forceinline__ u64 pack2(float a, float b) {
    u64 r;
    asm("mov.b64 %0, {%1, %2};" : "=l"(r) : "f"(a), "f"(b));
    return r;
}
__device__ __forceinline__ void fma2(u64 &d, u64 a, u64 b) {
    asm("fma.rn.f32x2 %0, %1, %2, %0;" : "+l"(d) : "l"(a), "l"(b));
}
__device__ __forceinline__ void unpack2(float &lo, float &hi, u64 v) {
    asm("mov.b64 {%0, %1}, %2;" : "=f"(lo), "=f"(hi) : "l"(v));
}

// Dynamic smem (34,816 B): sdict float[KK*EE] (32 KB, natural layout), snrm float[KK] (2 KB)
__global__ void __launch_bounds__(NT) vq_kernel(const float* __restrict__ mu,
                                                const float* __restrict__ dict,
                                                float* __restrict__ out)
{
    extern __shared__ float smem_f[];
    float* sdict = smem_f;
    float* snrm  = smem_f + KK * EE;

    const int c = blockIdx.x;
    const int t = threadIdx.x;

    // ---- this thread's 2 batch rows (t, t+256), packed pairwise over e ----
    u64 muA[EE / 2], muB[EE / 2];
    {
        const float* m0 = mu + (size_t)t         * (CC * EE) + c * EE;
        const float* m1 = mu + (size_t)(t + 256) * (CC * EE) + c * EE;
#pragma unroll
        for (int e = 0; e < EE; e += 4) {
            float4 a = *(const float4*)(m0 + e);
            float4 b = *(const float4*)(m1 + e);
            muA[e / 2] = pack2(a.x, a.y);  muA[e / 2 + 1] = pack2(a.z, a.w);
            muB[e / 2] = pack2(b.x, b.y);  muB[e / 2 + 1] = pack2(b.z, b.w);
        }
    }

    // ---- dict[c] -> smem (natural layout) ----
    {
        const float4* g = (const float4*)(dict + (size_t)c * KK * EE);
        float4* sd4 = (float4*)sdict;
#pragma unroll 4
        for (int i = t; i < KK * EE / 4; i += NT) sd4[i] = g[i];
    }
    __syncthreads();

    // ---- -0.5 * ||d_k||^2 ----
#pragma unroll
    for (int k = t; k < KK; k += NT) {
        const float4* dv = (const float4*)(sdict + k * EE);
        float s = 0.f;
#pragma unroll
        for (int j = 0; j < 4; j++) {
            float4 v = dv[j];
            s = fmaf(v.x, v.x, s); s = fmaf(v.y, v.y, s);
            s = fmaf(v.z, v.z, s); s = fmaf(v.w, v.w, s);
        }
        snrm[k] = -0.5f * s;
    }
    __syncthreads();

    // ---- one_hot zero cursor: col4 = t&127 of rows 2*it + (t>>7) ----
    const float4 z4 = make_float4(0.f, 0.f, 0.f, 0.f);
    float4* ohp = (float4*)(out + OH_OFF)
                + (size_t)(t >> 7) * (CC * KK / 4)
                + (size_t)c * (KK / 4) + (t & 127);
    const size_t OH_STEP = 2 * ((size_t)CC * KK / 4);   // 2 batch rows per iter

    // ---- main argmax loop (k-pairs), zero stores interleaved ----
    float best0 = -3.4e38f, best1 = -3.4e38f;
    int i0 = 0, i1 = 0;
    const ulonglong2* dq = (const ulonglong2*)sdict;    // 8 per k-pair

    for (int it = 0; it < KK / 2; ++it) {
        const int k = 2 * it;
        *ohp = z4; ohp += OH_STEP;                      // fire-and-forget zero

        const float n0 = snrm[k], n1 = snrm[k + 1];
        float lo, hi;

        u64 a0, a1, a2, a3;
        {   // k
            ulonglong2 q0 = dq[0], q1 = dq[1], q2 = dq[2], q3 = dq[3];
            a0 = pack2(n0, 0.f); a1 = a0;
            fma2(a0, muA[0], q0.x); fma2(a1, muB[0], q0.x);
            fma2(a0, muA[1], q0.y); fma2(a1, muB[1], q0.y);
            fma2(a0, muA[2], q1.x); fma2(a1, muB[2], q1.x);
            fma2(a0, muA[3], q1.y); fma2(a1, muB[3], q1.y);
            fma2(a0, muA[4], q2.x); fma2(a1, muB[4], q2.x);
            fma2(a0, muA[5], q2.y); fma2(a1, muB[5], q2.y);
            fma2(a0, muA[6], q3.x); fma2(a1, muB[6], q3.x);
            fma2(a0, muA[7], q3.y); fma2(a1, muB[7], q3.y);
        }
        {   // k+1
            ulonglong2 q4 = dq[4], q5 = dq[5], q6 = dq[6], q7 = dq[7];
            a2 = pack2(n1, 0.f); a3 = a2;
            fma2(a2, muA[0], q4.x); fma2(a3, muB[0], q4.x);
            fma2(a2, muA[1], q4.y); fma2(a3, muB[1], q4.y);
            fma2(a2, muA[2], q5.x); fma2(a3, muB[2], q5.x);
            fma2(a2, muA[3], q5.y); fma2(a3, muB[3], q5.y);
            fma2(a2, muA[4], q6.x); fma2(a3, muB[4], q6.x);
            fma2(a2, muA[5], q6.y); fma2(a3, muB[5], q6.y);
            fma2(a2, muA[6], q7.x); fma2(a3, muB[6], q7.x);
            fma2(a2, muA[7], q7.y); fma2(a3, muB[7], q7.y);
        }

        // ---- tournament bookkeeping: local k-vs-k+1 pick (SEL, pred-as-data),
        //      then ONE loop-carried update per row. Strict '>' keeps first-min ties.
        {
            unpack2(lo, hi, a0); const float s0 = lo + hi;   // row r0, k
            unpack2(lo, hi, a2); const float s2 = lo + hi;   // row r0, k+1
            const bool  pA = s2 > s0;
            const float sA = pA ? s2 : s0;
            const int   kA = pA ? (k + 1) : k;
            const bool  qA = sA > best0;
            best0 = qA ? sA : best0;
            i0    = qA ? kA : i0;
        }
        {
            unpack2(lo, hi, a1); const float s1 = lo + hi;   // row r1, k
            unpack2(lo, hi, a3); const float s3 = lo + hi;   // row r1, k+1
            const bool  pB = s3 > s1;
            const float sB = pB ? s3 : s1;
            const int   kB = pB ? (k + 1) : k;
            const bool  qB = sB > best1;
            best1 = qB ? sB : best1;
            i1    = qB ? kB : i1;
        }

        dq += 8;
    }

    __syncthreads();   // all zero-stores issued before the ones land

    // ---- write z and z_embed; scatter ones ----
    {
        const float* v = sdict + i0 * EE;
        size_t off = (size_t)t * (CC * EE) + c * EE;
#pragma unroll
        for (int e = 0; e < EE; e += 4) {
            float4 vv = *(const float4*)(v + e);
            float mx, my, mz, mw;
            unpack2(mx, my, muA[e / 2]);
            unpack2(mz, mw, muA[e / 2 + 1]);
            float4 zz;
            zz.x = mx + (vv.x - mx); zz.y = my + (vv.y - my);
            zz.z = mz + (vv.z - mz); zz.w = mw + (vv.w - mw);
            *(float4*)(out + Z_OFF  + off + e) = zz;
            *(float4*)(out + ZE_OFF + off + e) = vv;
        }
        out[OH_OFF + (size_t)t * (CC * KK) + (size_t)c * KK + i0] = 1.0f;
    }
    {
        const float* v = sdict + i1 * EE;
        size_t off = (size_t)(t + 256) * (CC * EE) + c * EE;
#pragma unroll
        for (int e = 0; e < EE; e += 4) {
            float4 vv = *(const float4*)(v + e);
            float mx, my, mz, mw;
            unpack2(mx, my, muB[e / 2]);
            unpack2(mz, mw, muB[e / 2 + 1]);
            float4 zz;
            zz.x = mx + (vv.x - mx); zz.y = my + (vv.y - my);
            zz.z = mz + (vv.z - mz); zz.w = mw + (vv.w - mw);
            *(float4*)(out + Z_OFF  + off + e) = zz;
            *(float4*)(out + ZE_OFF + off + e) = vv;
        }
        out[OH_OFF + (size_t)(t + 256) * (CC * KK) + (size_t)c * KK + i1] = 1.0f;
    }
}

extern "C" void kernel_launch(void* const* d_in, const int* in_sizes, int n_in,
                              void* d_out, int out_size)
{
    (void)in_sizes; (void)n_in; (void)out_size;
    const float* mu   = (const float*)d_in[0];
    const float* dict = (const float*)d_in[1];
    float* out = (float*)d_out;

    const int smem = (KK * EE + KK) * 4;   // 34,816 bytes
    cudaFuncSetAttribute(vq_kernel, cudaFuncAttributeMaxDynamicSharedMemorySize, smem);
    vq_kernel<<<CC, NT, smem>>>(mu, dict, out);
}

// round 11
// speedup vs baseline: 1.4796x; 1.0662x over previous
#include <cuda_runtime.h>

#define BB   512
#define CC   512
#define KK   512
#define EE   16
#define NT   128

#define Z_OFF   0
#define ZE_OFF  ((size_t)BB * CC * EE)            // 4,194,304 floats
#define OH_OFF  ((size_t)2 * BB * CC * EE)        // 8,388,608 floats

typedef unsigned long long u64;

__device__ __forceinline__ u64 pack2(float a, float b) {
    u64 r;
    asm("mov.b64 %0, {%1, %2};" : "=l"(r) : "f"(a), "f"(b));
    return r;
}
__device__ __forceinline__ void fma2(u64 &d, u64 a, u64 b) {
    asm("fma.rn.f32x2 %0, %1, %2, %0;" : "+l"(d) : "l"(a), "l"(b));
}
__device__ __forceinline__ void unpack2(float &lo, float &hi, u64 v) {
    asm("mov.b64 {%0, %1}, %2;" : "=f"(lo), "=f"(hi) : "l"(v));
}

// Dynamic smem (34,816 B): sdict float[KK*EE] (32 KB, natural layout), snrm float[KK] (2 KB)
__global__ void __launch_bounds__(NT, 4) vq_kernel(const float* __restrict__ mu,
                                                   const float* __restrict__ dict,
                                                   float* __restrict__ out)
{
    extern __shared__ float smem_f[];
    float* sdict = smem_f;
    float* snrm  = smem_f + KK * EE;

    const int c = blockIdx.x;
    const int t = threadIdx.x;

    // ---- this thread's 4 batch rows, packed pairwise over e ----
    u64 muA[EE / 2], muB[EE / 2], muC[EE / 2], muD[EE / 2];
    {
        const float* m0 = mu + (size_t)(t)       * (CC * EE) + c * EE;
        const float* m1 = mu + (size_t)(t + 128) * (CC * EE) + c * EE;
        const float* m2 = mu + (size_t)(t + 256) * (CC * EE) + c * EE;
        const float* m3 = mu + (size_t)(t + 384) * (CC * EE) + c * EE;
#pragma unroll
        for (int e = 0; e < EE; e += 4) {
            float4 a = *(const float4*)(m0 + e);
            float4 b = *(const float4*)(m1 + e);
            float4 x = *(const float4*)(m2 + e);
            float4 y = *(const float4*)(m3 + e);
            muA[e / 2] = pack2(a.x, a.y);  muA[e / 2 + 1] = pack2(a.z, a.w);
            muB[e / 2] = pack2(b.x, b.y);  muB[e / 2 + 1] = pack2(b.z, b.w);
            muC[e / 2] = pack2(x.x, x.y);  muC[e / 2 + 1] = pack2(x.z, x.w);
            muD[e / 2] = pack2(y.x, y.y);  muD[e / 2 + 1] = pack2(y.z, y.w);
        }
    }

    // ---- dict[c] -> smem (natural layout) ----
    {
        const float4* g = (const float4*)(dict + (size_t)c * KK * EE);
        float4* sd4 = (float4*)sdict;
#pragma unroll 4
        for (int i = t; i < KK * EE / 4; i += NT) sd4[i] = g[i];
    }
    __syncthreads();

    // ---- -0.5 * ||d_k||^2 ----
#pragma unroll
    for (int k = t; k < KK; k += NT) {
        const float4* dv = (const float4*)(sdict + k * EE);
        float s = 0.f;
#pragma unroll
        for (int j = 0; j < 4; j++) {
            float4 v = dv[j];
            s = fmaf(v.x, v.x, s); s = fmaf(v.y, v.y, s);
            s = fmaf(v.z, v.z, s); s = fmaf(v.w, v.w, s);
        }
        snrm[k] = -0.5f * s;
    }
    __syncthreads();

    // ---- one_hot zero cursors: rows (2it, 2it+1), thread t covers col4 t ----
    const float4 z4 = make_float4(0.f, 0.f, 0.f, 0.f);
    const size_t ROWF4 = (size_t)CC * KK / 4;
    float4* ohp0 = (float4*)(out + OH_OFF) + (size_t)c * (KK / 4) + t;
    float4* ohp1 = ohp0 + ROWF4;
    const size_t OH_STEP = 2 * ROWF4;

    // ---- main argmax loop (k-pairs): 64 FFMA2 per 5 LDS ----
    float best0 = -3.4e38f, best1 = -3.4e38f, best2 = -3.4e38f, best3 = -3.4e38f;
    int i0 = 0, i1 = 0, i2 = 0, i3 = 0;
    const ulonglong2* dq = (const ulonglong2*)sdict;    // 8 per k-pair

    for (int it = 0; it < KK / 2; ++it) {
        const int k = 2 * it;
        *ohp0 = z4; ohp0 += OH_STEP;                    // fire-and-forget zeros
        *ohp1 = z4; ohp1 += OH_STEP;

        const float2 nn = *(const float2*)(snrm + k);
        float lo, hi, s;

        u64 a0, a1, a2, a3, b0, b1, b2, b3;
        {   // k: rows A,B,C,D
            ulonglong2 q0 = dq[0], q1 = dq[1], q2 = dq[2], q3 = dq[3];
            a0 = pack2(nn.x, 0.f); a1 = a0; a2 = a0; a3 = a0;
            fma2(a0, muA[0], q0.x); fma2(a1, muB[0], q0.x); fma2(a2, muC[0], q0.x); fma2(a3, muD[0], q0.x);
            fma2(a0, muA[1], q0.y); fma2(a1, muB[1], q0.y); fma2(a2, muC[1], q0.y); fma2(a3, muD[1], q0.y);
            fma2(a0, muA[2], q1.x); fma2(a1, muB[2], q1.x); fma2(a2, muC[2], q1.x); fma2(a3, muD[2], q1.x);
            fma2(a0, muA[3], q1.y); fma2(a1, muB[3], q1.y); fma2(a2, muC[3], q1.y); fma2(a3, muD[3], q1.y);
            fma2(a0, muA[4], q2.x); fma2(a1, muB[4], q2.x); fma2(a2, muC[4], q2.x); fma2(a3, muD[4], q2.x);
            fma2(a0, muA[5], q2.y); fma2(a1, muB[5], q2.y); fma2(a2, muC[5], q2.y); fma2(a3, muD[5], q2.y);
            fma2(a0, muA[6], q3.x); fma2(a1, muB[6], q3.x); fma2(a2, muC[6], q3.x); fma2(a3, muD[6], q3.x);
            fma2(a0, muA[7], q3.y); fma2(a1, muB[7], q3.y); fma2(a2, muC[7], q3.y); fma2(a3, muD[7], q3.y);
        }
        {   // k+1: rows A,B,C,D
            ulonglong2 q4 = dq[4], q5 = dq[5], q6 = dq[6], q7 = dq[7];
            b0 = pack2(nn.y, 0.f); b1 = b0; b2 = b0; b3 = b0;
            fma2(b0, muA[0], q4.x); fma2(b1, muB[0], q4.x); fma2(b2, muC[0], q4.x); fma2(b3, muD[0], q4.x);
            fma2(b0, muA[1], q4.y); fma2(b1, muB[1], q4.y); fma2(b2, muC[1], q4.y); fma2(b3, muD[1], q4.y);
            fma2(b0, muA[2], q5.x); fma2(b1, muB[2], q5.x); fma2(b2, muC[2], q5.x); fma2(b3, muD[2], q5.x);
            fma2(b0, muA[3], q5.y); fma2(b1, muB[3], q5.y); fma2(b2, muC[3], q5.y); fma2(b3, muD[3], q5.y);
            fma2(b0, muA[4], q6.x); fma2(b1, muB[4], q6.x); fma2(b2, muC[4], q6.x); fma2(b3, muD[4], q6.x);
            fma2(b0, muA[5], q6.y); fma2(b1, muB[5], q6.y); fma2(b2, muC[5], q6.y); fma2(b3, muD[5], q6.y);
            fma2(b0, muA[6], q7.x); fma2(b1, muB[6], q7.x); fma2(b2, muC[6], q7.x); fma2(b3, muD[6], q7.x);
            fma2(b0, muA[7], q7.y); fma2(b1, muB[7], q7.y); fma2(b2, muC[7], q7.y); fma2(b3, muD[7], q7.y);
        }

        // R2-style @P bookkeeping; strict '>' keeps first-min ties
        unpack2(lo, hi, a0); s = lo + hi; if (s > best0) { best0 = s; i0 = k; }
        unpack2(lo, hi, b0); s = lo + hi; if (s > best0) { best0 = s; i0 = k + 1; }
        unpack2(lo, hi, a1); s = lo + hi; if (s > best1) { best1 = s; i1 = k; }
        unpack2(lo, hi, b1); s = lo + hi; if (s > best1) { best1 = s; i1 = k + 1; }
        unpack2(lo, hi, a2); s = lo + hi; if (s > best2) { best2 = s; i2 = k; }
        unpack2(lo, hi, b2); s = lo + hi; if (s > best2) { best2 = s; i2 = k + 1; }
        unpack2(lo, hi, a3); s = lo + hi; if (s > best3) { best3 = s; i3 = k; }
        unpack2(lo, hi, b3); s = lo + hi; if (s > best3) { best3 = s; i3 = k + 1; }

        dq += 8;
    }

    __syncthreads();   // all zero-stores issued before the ones land

    // ---- write z / z_embed; scatter ones ----
    const int  rows[4] = { t, t + 128, t + 256, t + 384 };
    const int  idxs[4] = { i0, i1, i2, i3 };
    const u64* mus[4]  = { muA, muB, muC, muD };
#pragma unroll
    for (int r = 0; r < 4; ++r) {
        const float* v = sdict + idxs[r] * EE;
        size_t off = (size_t)rows[r] * (CC * EE) + c * EE;
#pragma unroll
        for (int e = 0; e < EE; e += 4) {
            float4 vv = *(const float4*)(v + e);
            float mx, my, mz, mw;
            unpack2(mx, my, mus[r][e / 2]);
            unpack2(mz, mw, mus[r][e / 2 + 1]);
            float4 zz;
            zz.x = mx + (vv.x - mx); zz.y = my + (vv.y - my);
            zz.z = mz + (vv.z - mz); zz.w = mw + (vv.w - mw);
            *(float4*)(out + Z_OFF  + off + e) = zz;
            *(float4*)(out + ZE_OFF + off + e) = vv;
        }
        out[OH_OFF + (size_t)rows[r] * (CC * KK) + (size_t)c * KK + idxs[r]] = 1.0f;
    }
}

extern "C" void kernel_launch(void* const* d_in, const int* in_sizes, int n_in,
                              void* d_out, int out_size)
{
    (void)in_sizes; (void)n_in; (void)out_size;
    const float* mu   = (const float*)d_in[0];
    const float* dict = (const float*)d_in[1];
    float* out = (float*)d_out;

    const int smem = (KK * EE + KK) * 4;   // 34,816 bytes
    cudaFuncSetAttribute(vq_kernel, cudaFuncAttributeMaxDynamicSharedMemorySize, smem);
    vq_kernel<<<CC, NT, smem>>>(mu, dict, out);
}